// round 13
// baseline (speedup 1.0000x reference)
#include <cuda_runtime.h>
#include <cstdint>

// Problem constants
#define NB   1024   // batch
#define NT   256    // time steps
#define ND   64     // embedding dim
#define NH   128    // hidden dim
#define N2H  256    // 2*H
#define RPB  4      // rows per gru tile
#define NTIL (NB / RPB)   // 256 tiles
#define GRUB 148    // persistent gru blocks (1/SM)
#define WST  133    // padded k-stride for transposed Whc (bank stride 5 -> conflict-free)
#define CH   16     // timesteps per precompute chunk
#define XST2 20     // padded row-stride for transposed x stage (16 rows + 4 pad)

// Scratch (device globals; rewritten deterministically each launch)
__device__ float g_Xg[(size_t)NB * NT * N2H];  // 256 MB
__device__ float g_Xc[(size_t)NB * NT * NH];   // 128 MB
__device__ int   g_perm[NB];
__device__ int   g_tile_ctr;

// ---------------------------------------------------------------------------
// packed f32x2 helpers (sm_100+): ptxas won't emit FFMA2 from C++, so PTX.
// ---------------------------------------------------------------------------
__device__ __forceinline__ uint64_t dup2(float w) {
    uint64_t r; uint32_t wi = __float_as_uint(w);
    asm("mov.b64 %0, {%1, %1};" : "=l"(r) : "r"(wi));
    return r;
}
__device__ __forceinline__ void fma2(uint64_t& d, uint64_t a, uint64_t b) {
    asm("fma.rn.f32x2 %0, %1, %2, %0;" : "+l"(d) : "l"(a), "l"(b));
}
__device__ __forceinline__ uint64_t add2(uint64_t a, uint64_t b) {
    uint64_t r; asm("add.rn.f32x2 %0, %1, %2;" : "=l"(r) : "l"(a), "l"(b));
    return r;
}
__device__ __forceinline__ float2 unpk(uint64_t v) {
    uint32_t lo, hi;
    asm("mov.b64 {%0, %1}, %2;" : "=r"(lo), "=r"(hi) : "l"(v));
    return make_float2(__uint_as_float(lo), __uint_as_float(hi));
}

__device__ __forceinline__ float sigf(float x) {
    return __fdividef(1.f, 1.f + __expf(-x));
}
__device__ __forceinline__ float tanhfast(float x) {
    float e = __expf(2.f * x);          // inf for large x -> result 1
    return 1.f - __fdividef(2.f, e + 1.f);
}

// ---------------------------------------------------------------------------
// Single-launch counting sort of batch rows by seq_len, DESCENDING (LPT);
// also resets the persistent-gru tile counter.
// ---------------------------------------------------------------------------
__global__ __launch_bounds__(NB, 1)
void sort_all_kernel(const int* __restrict__ lens) {
    __shared__ int hist[256];
    __shared__ int off[256];
    const int tid = threadIdx.x;
    if (tid == 0) g_tile_ctr = 0;
    if (tid < 256) hist[tid] = 0;
    __syncthreads();
    const int l = min(max(lens[tid], 0), 255);
    atomicAdd(&hist[l], 1);
    __syncthreads();
    if (tid == 0) {
        int run = 0;
        for (int i = 255; i >= 0; --i) { off[i] = run; run += hist[i]; }
    }
    __syncthreads();
    int p = atomicAdd(&off[l], 1);
    g_perm[p] = tid;
}

// ---------------------------------------------------------------------------
// Kernel 1: precompute Xg = x @ Wxg + gate_bias, Xc = x @ Wxc + cand_bias
// One block per batch row b; chunks of 16 timesteps (halves per-k overhead);
// transposed x stage, packed f32x2 math, double-buffered embedding gather.
// ---------------------------------------------------------------------------
__global__ __launch_bounds__(256, 2)
void precompute_kernel(const int* __restrict__ item_his,
                       const int* __restrict__ seq_lens,
                       const float* __restrict__ embedding,
                       const float* __restrict__ gate_kernel,
                       const float* __restrict__ gate_bias,
                       const float* __restrict__ cand_kernel,
                       const float* __restrict__ cand_bias) {
    extern __shared__ float sm[];
    float* Wxg = sm;                    // 64*256 = 16384
    float* Wxc = Wxg + 64 * N2H;        // 64*128 = 8192
    float* xsT = Wxc + 64 * NH;         // 64*XST2 = 1280  (xsT[k*XST2 + r])

    const int tid = threadIdx.x;
    const int b   = blockIdx.x;
    const int len = seq_lens[b];

    for (int i = tid; i < (64 * N2H) / 4; i += 256)
        ((float4*)Wxg)[i] = ((const float4*)gate_kernel)[i];
    for (int i = tid; i < (64 * NH) / 4; i += 256)
        ((float4*)Wxc)[i] = ((const float4*)cand_kernel)[i];
    __syncthreads();

    if (len <= 0) return;

    const float gb = gate_bias[tid];
    const int   cc = tid & 127;
    const int   r0 = (tid >> 7) * 8;    // 0 or 8 (Xc row group)
    const float cb = cand_bias[cc];

    const int j0 = tid >> 5;         // gather rows j0 and j0+8
    const int e  = (tid & 31) * 2;   // gather k pair

    // prefetch chunk 0 (two rows per thread)
    float2 va = make_float2(0.f, 0.f), vb = make_float2(0.f, 0.f);
    if (j0 < len) {
        int idx = item_his[b * NT + j0];
        va = *(const float2*)&embedding[(size_t)idx * ND + e];
    }
    if (j0 + 8 < len) {
        int idx = item_his[b * NT + j0 + 8];
        vb = *(const float2*)&embedding[(size_t)idx * ND + e];
    }

    for (int t0 = 0; t0 < len; t0 += CH) {
        xsT[(e + 0) * XST2 + j0]     = va.x;
        xsT[(e + 1) * XST2 + j0]     = va.y;
        xsT[(e + 0) * XST2 + j0 + 8] = vb.x;
        xsT[(e + 1) * XST2 + j0 + 8] = vb.y;
        __syncthreads();

        // prefetch next chunk (overlaps with compute below)
        {
            int ta = t0 + CH + j0;
            int tb = ta + 8;
            va = make_float2(0.f, 0.f);
            vb = make_float2(0.f, 0.f);
            if (ta < len) {
                int idx = item_his[b * NT + ta];
                va = *(const float2*)&embedding[(size_t)idx * ND + e];
            }
            if (tb < len) {
                int idx = item_his[b * NT + tb];
                vb = *(const float2*)&embedding[(size_t)idx * ND + e];
            }
        }

        // ---- Xg: thread == gate column (0..255), 16 rows as 8 packed pairs
        uint64_t a[8];
        #pragma unroll
        for (int p = 0; p < 8; p++) a[p] = 0;
        #pragma unroll 4
        for (int k = 0; k < 64; k++) {
            uint64_t d = dup2(Wxg[k * N2H + tid]);
            const ulonglong2* xp = (const ulonglong2*)&xsT[k * XST2];
            ulonglong2 h0 = xp[0], h1 = xp[1], h2 = xp[2], h3 = xp[3];
            fma2(a[0], h0.x, d); fma2(a[1], h0.y, d);
            fma2(a[2], h1.x, d); fma2(a[3], h1.y, d);
            fma2(a[4], h2.x, d); fma2(a[5], h2.y, d);
            fma2(a[6], h3.x, d); fma2(a[7], h3.y, d);
        }
        #pragma unroll
        for (int p = 0; p < 8; p++) {
            float2 v = unpk(a[p]);
            int t = t0 + 2 * p;
            if (t < len)
                g_Xg[((size_t)b * NT + t) * N2H + tid] = v.x + gb;
            if (t + 1 < len)
                g_Xg[((size_t)b * NT + t + 1) * N2H + tid] = v.y + gb;
        }

        // ---- Xc: column = tid&127, rows r0..r0+7 as 4 packed pairs
        uint64_t bc[4];
        #pragma unroll
        for (int p = 0; p < 4; p++) bc[p] = 0;
        #pragma unroll 4
        for (int k = 0; k < 64; k++) {
            uint64_t d = dup2(Wxc[k * NH + cc]);
            const ulonglong2* xp = (const ulonglong2*)&xsT[k * XST2 + r0];
            ulonglong2 h0 = xp[0], h1 = xp[1];
            fma2(bc[0], h0.x, d); fma2(bc[1], h0.y, d);
            fma2(bc[2], h1.x, d); fma2(bc[3], h1.y, d);
        }
        #pragma unroll
        for (int p = 0; p < 4; p++) {
            float2 v = unpk(bc[p]);
            int t = t0 + r0 + 2 * p;
            if (t < len)
                g_Xc[((size_t)b * NT + t) * NH + cc] = v.x + cb;
            if (t + 1 < len)
                g_Xc[((size_t)b * NT + t + 1) * NH + cc] = v.y + cb;
        }
        __syncthreads();
    }
}

// ---------------------------------------------------------------------------
// Kernel 2: recurrence. PERSISTENT: 148 blocks (1/SM), 1024 threads; weights
// loaded once, then tiles pulled from a global counter in sorted (LPT) order.
// Phase A: thread = (col pair {c2, c2+128}, k-eighth), weights in registers.
// Phase C: thread = (col pair {cc2, cc2+64}, k-sixteenth), weights from smem.
// ---------------------------------------------------------------------------
__global__ __launch_bounds__(1024, 1)
void gru_kernel(const int* __restrict__ seq_lens,
                const float* __restrict__ gate_kernel,
                const float* __restrict__ cand_kernel,
                float* __restrict__ out) {
    extern __shared__ float sm[];
    float* WcT   = sm;                    // 128*133 = 17024 floats
    float* hsT   = WcT + 128 * WST;       // 512  (hsT[k*4 + r])
    float* rhT   = hsT + 512;             // 512
    float* us    = rhT + 512;             // 512
    float* psA_r = us + 512;              // 8 subs * 128 cols * 4 = 4096
    float* psA_u = psA_r + 4096;          // 4096
    float* pcC0  = psA_u + 4096;          // 16 subs * 64 cols * 4 = 4096
    float* pcC1  = pcC0 + 4096;           // 4096
    __shared__ int s_len[RPB];
    __shared__ int s_ob[RPB];
    __shared__ int s_maxlen;
    __shared__ int s_tile;

    const int tid = threadIdx.x;

    // Transposed Whc into smem: WcT[c*WST+k] = Whc[k][c]  (once)
    {
        const float4* Wc4 = (const float4*)(cand_kernel + 64 * NH);   // [k][c]
        for (int i = tid; i < (NH * NH) / 4; i += 1024) {
            int k = i >> 5, c4 = (i & 31) * 4;
            float4 w = Wc4[i];
            WcT[(c4 + 0) * WST + k] = w.x;
            WcT[(c4 + 1) * WST + k] = w.y;
            WcT[(c4 + 2) * WST + k] = w.z;
            WcT[(c4 + 3) * WST + k] = w.w;
        }
    }

    // ---- Phase A mapping & register weights (once)
    const int c2   = tid & 127;      // column pair {c2, c2+128}
    const int subA = tid >> 7;       // k-eighth 0..7
    const int k0a  = subA * 16;
    float wA0[16], wA1[16];
    {
        const float* Wg = gate_kernel + 64 * N2H;   // [k][c] rows 64..191
        #pragma unroll
        for (int i = 0; i < 16; i++) {
            wA0[i] = __ldg(&Wg[(k0a + i) * N2H + c2]);
            wA1[i] = __ldg(&Wg[(k0a + i) * N2H + c2 + 128]);
        }
    }

    // ---- Phase C mapping (once)
    const int cc2  = tid & 63;       // column pair {cc2, cc2+64}
    const int subC = tid >> 6;       // k-sixteenth 0..15
    const int k0c  = subC * 8;
    const float* wcp0 = &WcT[cc2 * WST + k0c];
    const float* wcp1 = &WcT[(cc2 + 64) * WST + k0c];

    const int cA = tid & 255, pA = (tid >> 8) & 1;
    const int pA2 = 2 * pA;
    const int cE = tid & 127, pC = (tid >> 7) & 1;
    const int pC2 = 2 * pC;

    for (;;) {
        // ---- grab next tile (LPT: tiles are length-sorted descending)
        if (tid == 0) s_tile = atomicAdd(&g_tile_ctr, 1);
        __syncthreads();   // also orders previous tile's out-reads before hsT zero
        const int tile = s_tile;
        if (tile >= NTIL) break;

        for (int i = tid; i < RPB * NH; i += 1024) hsT[i] = 0.f;
        if (tid == 0) {
            int m = 0;
            #pragma unroll
            for (int jj = 0; jj < RPB; jj++) {
                int ob = g_perm[tile * RPB + jj];
                int l  = seq_lens[ob];
                s_ob[jj] = ob; s_len[jj] = l;
                m = max(m, l);
            }
            s_maxlen = m;
        }
        __syncthreads();
        const int maxlen = s_maxlen;

        // Per-tile epilogue roles
        int egA0 = 0, egA1 = 0;
        if (tid < 512) {
            egA0 = s_ob[pA2]     * NT * N2H + cA;
            egA1 = s_ob[pA2 + 1] * NT * N2H + cA;
        }
        int egC0 = 0, egC1 = 0, lnC0 = 0, lnC1 = 0;
        if (tid < 256) {
            egC0 = s_ob[pC2]     * NT * NH + cE;
            egC1 = s_ob[pC2 + 1] * NT * NH + cE;
            lnC0 = s_len[pC2];
            lnC1 = s_len[pC2 + 1];
        }

        for (int t = 0; t < maxlen; t++) {
            // Distributed prefetch of input contributions
            float xg0 = 0.f, xg1 = 0.f, xc0 = 0.f, xc1 = 0.f;
            if (tid < 512) {
                xg0 = __ldg(&g_Xg[(size_t)egA0 + (size_t)t * N2H]);
                xg1 = __ldg(&g_Xg[(size_t)egA1 + (size_t)t * N2H]);
            }
            if (tid < 256) {
                xc0 = __ldg(&g_Xc[(size_t)egC0 + (size_t)t * NH]);
                xc1 = __ldg(&g_Xc[(size_t)egC1 + (size_t)t * NH]);
            }

            // ---- Phase A main: partial h @ Whg (k in [k0a,k0a+16), cols c2 & c2+128)
            uint64_t a00 = 0, a01 = 0, a10 = 0, a11 = 0;
            #pragma unroll
            for (int i = 0; i < 16; i++) {
                ulonglong2 hk = *(const ulonglong2*)&hsT[(k0a + i) * 4];
                uint64_t d0 = dup2(wA0[i]);
                uint64_t d1 = dup2(wA1[i]);
                fma2(a00, hk.x, d0); fma2(a01, hk.y, d0);
                fma2(a10, hk.x, d1); fma2(a11, hk.y, d1);
            }
            {
                ulonglong2 v1; v1.x = a00; v1.y = a01;
                ulonglong2 v2; v2.x = a10; v2.y = a11;
                ((ulonglong2*)psA_r)[subA * 128 + c2] = v1;
                ((ulonglong2*)psA_u)[subA * 128 + c2] = v2;
            }
            __syncthreads();

            // ---- Phase A epilogue (tid < 512): reduce 8 partials, sigmoid, rh/us
            if (tid < 512) {
                const uint64_t* pp = (const uint64_t*)(cA < 128 ? psA_r : psA_u);
                const int cl = cA & 127;
                uint64_t s = pp[(0 * 128 + cl) * 2 + pA];
                #pragma unroll
                for (int ss = 1; ss < 8; ss++)
                    s = add2(s, pp[(ss * 128 + cl) * 2 + pA]);
                float2 v = unpk(s);
                float g0 = sigf(v.x + xg0);
                float g1 = sigf(v.y + xg1);
                if (cA < 128) {
                    float2 hv = *(const float2*)&hsT[cA * 4 + pA2];
                    float2 rv; rv.x = g0 * hv.x; rv.y = g1 * hv.y;
                    *(float2*)&rhT[cA * 4 + pA2] = rv;
                } else {
                    float2 uv; uv.x = g0; uv.y = g1;
                    *(float2*)&us[(cA - 128) * 4 + pA2] = uv;
                }
            }
            __syncthreads();

            // ---- Phase C main: partial rh @ Whc (k in [k0c,k0c+8), cols cc2 & cc2+64)
            uint64_t b00 = 0, b01 = 0, b10 = 0, b11 = 0;
            #pragma unroll
            for (int jv = 0; jv < 8; jv++) {
                ulonglong2 hk = *(const ulonglong2*)&rhT[(k0c + jv) * 4];
                uint64_t d0 = dup2(wcp0[jv]);
                uint64_t d1 = dup2(wcp1[jv]);
                fma2(b00, hk.x, d0); fma2(b01, hk.y, d0);
                fma2(b10, hk.x, d1); fma2(b11, hk.y, d1);
            }
            {
                ulonglong2 v1; v1.x = b00; v1.y = b01;
                ulonglong2 v2; v2.x = b10; v2.y = b11;
                ((ulonglong2*)pcC0)[subC * 64 + cc2] = v1;
                ((ulonglong2*)pcC1)[subC * 64 + cc2] = v2;
            }
            __syncthreads();

            // ---- Phase C epilogue (tid < 256): reduce 16 partials, tanh, h update
            if (tid < 256) {
                const uint64_t* pp = (const uint64_t*)(cE < 64 ? pcC0 : pcC1);
                const int cl = cE & 63;
                uint64_t s = pp[(0 * 64 + cl) * 2 + pC];
                #pragma unroll
                for (int ss = 1; ss < 16; ss++)
                    s = add2(s, pp[(ss * 64 + cl) * 2 + pC]);
                float2 v = unpk(s);
                float cn0 = tanhfast(v.x + xc0);
                float cn1 = tanhfast(v.y + xc1);
                float2 uv = *(const float2*)&us[cE * 4 + pC2];
                float2 hv = *(const float2*)&hsT[cE * 4 + pC2];
                float h0 = uv.x * hv.x + (1.f - uv.x) * cn0;
                float h1 = uv.y * hv.y + (1.f - uv.y) * cn1;
                float2 hn;
                hn.x = (t < lnC0) ? h0 : hv.x;
                hn.y = (t < lnC1) ? h1 : hv.y;
                *(float2*)&hsT[cE * 4 + pC2] = hn;
            }
            __syncthreads();
        }

        // Scatter final h to original batch positions: hsT[k*4+r] = h[r][k]
        for (int i = tid; i < RPB * NH; i += 1024) {
            int k = i >> 2, r = i & 3;
            out[s_ob[r] * NH + k] = hsT[i];
        }
    }
}

// ---------------------------------------------------------------------------
extern "C" void kernel_launch(void* const* d_in, const int* in_sizes, int n_in,
                              void* d_out, int out_size) {
    const int*   item_his    = (const int*)d_in[0];
    const int*   seq_lens    = (const int*)d_in[1];
    const float* embedding   = (const float*)d_in[2];
    const float* gate_kernel = (const float*)d_in[3];
    const float* gate_bias   = (const float*)d_in[4];
    const float* cand_kernel = (const float*)d_in[5];
    const float* cand_bias   = (const float*)d_in[6];
    float* out = (float*)d_out;

    const int smem1 = (64 * N2H + 64 * NH + 64 * XST2) * sizeof(float);         // ~104 KB
    const int smem2 = (128 * WST + 512 * 3 + 4096 * 4) * sizeof(float);         // ~139 KB

    static bool attr_set = false;
    if (!attr_set) {
        cudaFuncSetAttribute(precompute_kernel,
                             cudaFuncAttributeMaxDynamicSharedMemorySize, smem1);
        cudaFuncSetAttribute(gru_kernel,
                             cudaFuncAttributeMaxDynamicSharedMemorySize, smem2);
        attr_set = true;
    }

    sort_all_kernel<<<1, NB>>>(seq_lens);
    precompute_kernel<<<NB, 256, smem1>>>(item_his, seq_lens, embedding,
                                          gate_kernel, gate_bias,
                                          cand_kernel, cand_bias);
    gru_kernel<<<GRUB, 1024, smem2>>>(seq_lens, gate_kernel, cand_kernel, out);
}